// round 14
// baseline (speedup 1.0000x reference)
#include <cuda_runtime.h>
#include <cuda_bf16.h>
#include <cstdint>
#include <math.h>

#define NTOK 4096
#define EDIM 1024
#define HID  4096
#define NLAYER 12
#define NHEAD 16
#define HDIM 64
#define BATCH 2048
#define VOC  32000
#define QKVN 3072

typedef __nv_bfloat16 bf16;

struct alignas(8) bf4 { __nv_bfloat162 a, b; };

// ---------------- scratch (device globals) ----------------
__device__ bf16 g_Wqkv_h[NLAYER * QKVN * EDIM];
__device__ bf16 g_Wqkv_l[NLAYER * QKVN * EDIM];
__device__ bf16 g_Wo_h [NLAYER * EDIM * EDIM];
__device__ bf16 g_Wo_l [NLAYER * EDIM * EDIM];
__device__ bf16 g_W1_h [NLAYER * HID * EDIM];
__device__ bf16 g_W1_l [NLAYER * HID * EDIM];
__device__ bf16 g_W2_h [NLAYER * EDIM * HID];
__device__ bf16 g_W2_l [NLAYER * EDIM * HID];
__device__ bf16 g_Ue_h [VOC * EDIM];
__device__ bf16 g_Ue_l [VOC * EDIM];
__device__ float g_QKV[NTOK * QKVN];
__device__ bf16  g_Xh [NTOK * EDIM];
__device__ bf16  g_Xl [NTOK * EDIM];
__device__ bf16  g_X2h[NTOK * EDIM];
__device__ bf16  g_X2l[NTOK * EDIM];
__device__ bf16  g_Oh [NTOK * EDIM];
__device__ bf16  g_Ol [NTOK * EDIM];
__device__ bf16  g_H1h[NTOK * HID];
__device__ bf16  g_H1l[NTOK * HID];
// flags: [QKV 0..31 | O 32..63 | X2 64..95 | H1 96..127 | X 128..159]
__device__ int   g_flags[160];

__device__ __forceinline__ void split2(float v, bf16& h, bf16& l) {
    h = __float2bfloat16(v);
    l = __float2bfloat16(v - __bfloat162float(h));
}

__device__ __forceinline__ int ldflag(const int* p) {
    int v; asm volatile("ld.global.cg.b32 %0, [%1];" : "=r"(v) : "l"(p)); return v;
}
__device__ __forceinline__ void spinwait(const int* p, int need) {
    while (ldflag(p) < need) __nanosleep(64);
}

// ---------------- weight transpose + split ----------------
__global__ void tconv_kernel(const float* __restrict__ src,
                             bf16* __restrict__ dhi, bf16* __restrict__ dlo,
                             int K, int N)
{
    __shared__ float t[64][33];
    const int z = blockIdx.z;
    src += (size_t)z * K * N;
    dhi += (size_t)z * K * N;
    dlo += (size_t)z * K * N;
    const int k0 = blockIdx.y * 64, n0 = blockIdx.x * 32;
    const int tx = threadIdx.x, ty = threadIdx.y;
#pragma unroll
    for (int j = 0; j < 8; j++)
        t[ty + 8 * j][tx] = src[(size_t)(k0 + ty + 8 * j) * N + n0 + tx];
    __syncthreads();
    const int s  = ty * 32 + tx;
    const int kq = s & 15;
    const int nb = s >> 4;
#pragma unroll
    for (int j = 0; j < 2; j++) {
        const int n = nb + 16 * j;
        float v0 = t[4 * kq + 0][n];
        float v1 = t[4 * kq + 1][n];
        float v2 = t[4 * kq + 2][n];
        float v3 = t[4 * kq + 3][n];
        bf16 h0, l0, h1, l1, h2, l2, h3, l3;
        split2(v0, h0, l0); split2(v1, h1, l1);
        split2(v2, h2, l2); split2(v3, h3, l3);
        bf4 ph, pl;
        ph.a.x = h0; ph.a.y = h1; ph.b.x = h2; ph.b.y = h3;
        pl.a.x = l0; pl.a.y = l1; pl.b.x = l2; pl.b.y = l3;
        size_t o = (size_t)(n0 + n) * K + k0 + 4 * kq;
        *(bf4*)&dhi[o] = ph;
        *(bf4*)&dlo[o] = pl;
    }
}

__global__ void tconv_qkv_kernel(const float* __restrict__ Wq,
                                 const float* __restrict__ Wk,
                                 const float* __restrict__ Wv,
                                 bf16* __restrict__ dhi, bf16* __restrict__ dlo)
{
    __shared__ float t[64][33];
    const int z = blockIdx.z;
    const int l = z / 48;
    const int rr = z % 48;
    const int which = rr / 16;
    const int h = rr % 16;
    const float* src = (which == 0 ? Wq : which == 1 ? Wk : Wv)
                       + ((size_t)(l * NHEAD + h) * EDIM) * HDIM;
    const int i0 = blockIdx.x * 32;
    const int k0 = blockIdx.y * 64;
    const int tx = threadIdx.x, ty = threadIdx.y;
#pragma unroll
    for (int j = 0; j < 8; j++)
        t[ty + 8 * j][tx] = src[(size_t)(k0 + ty + 8 * j) * HDIM + i0 + tx];
    __syncthreads();
    bf16* bh = dhi + (size_t)l * QKVN * EDIM;
    bf16* bl = dlo + (size_t)l * QKVN * EDIM;
    const int s  = ty * 32 + tx;
    const int kq = s & 15;
    const int nb = s >> 4;
#pragma unroll
    for (int j = 0; j < 2; j++) {
        const int ni = nb + 16 * j;
        float v0 = t[4 * kq + 0][ni];
        float v1 = t[4 * kq + 1][ni];
        float v2 = t[4 * kq + 2][ni];
        float v3 = t[4 * kq + 3][ni];
        bf16 h0, l0, h1, l1, h2, l2, h3, l3;
        split2(v0, h0, l0); split2(v1, h1, l1);
        split2(v2, h2, l2); split2(v3, h3, l3);
        bf4 ph, pl;
        ph.a.x = h0; ph.a.y = h1; ph.b.x = h2; ph.b.y = h3;
        pl.a.x = l0; pl.a.y = l1; pl.b.x = l2; pl.b.y = l3;
        int n = which * 1024 + h * 64 + i0 + ni;
        size_t o = (size_t)n * EDIM + k0 + 4 * kq;
        *(bf4*)&bh[o] = ph;
        *(bf4*)&bl[o] = pl;
    }
}

// ---------------- embedding ----------------
__global__ void embed_kernel(const int* __restrict__ tokens,
                             const float* __restrict__ emb,
                             const float* __restrict__ pos,
                             bf16* __restrict__ Xh, bf16* __restrict__ Xl)
{
    int idx = blockIdx.x * blockDim.x + threadIdx.x;
    int i  = idx / (EDIM / 4);
    int e4 = idx % (EDIM / 4);
    int tok = tokens[i];
    float4 a = ((const float4*)(emb + (size_t)tok * EDIM))[e4];
    float4 p = ((const float4*)(pos + (size_t)(i & 1) * EDIM))[e4];
    float r[4] = { a.x + p.x, a.y + p.y, a.z + p.z, a.w + p.w };
    bf16 hh[4], ll[4];
#pragma unroll
    for (int j = 0; j < 4; j++) split2(r[j], hh[j], ll[j]);
    bf4 ph, pl;
    ph.a.x = hh[0]; ph.a.y = hh[1]; ph.b.x = hh[2]; ph.b.y = hh[3];
    pl.a.x = ll[0]; pl.a.y = ll[1]; pl.b.x = ll[2]; pl.b.y = ll[3];
    size_t o = (size_t)i * EDIM + e4 * 4;
    *(bf4*)&Xh[o] = ph;
    *(bf4*)&Xl[o] = pl;
}

// ---------------- GEMM config + MMA helpers ----------------
struct GCfg {
    const bf16 *Ah, *Al;
    const bf16 *Bh, *Bl;
    const float* bias;
    const bf16 *resh, *resl;
    float* Cf;
    bf16 *Ch, *Cl;
    int* outFlag;
    const int* inFlag;
    int lda, N, K, nbx, nTiles, ebits, inNeed, rowWaitMul;
};
// ebits: 1 BIAS, 2 RELU, 4 RES, 8 WF32, 16 WBF

#define MMA_BF16(d, a, b0, b1)                                             \
    asm volatile("mma.sync.aligned.m16n8k16.row.col.f32.bf16.bf16.f32 "    \
                 "{%0,%1,%2,%3},{%4,%5,%6,%7},{%8,%9},{%0,%1,%2,%3};"      \
                 : "+f"(d[0]), "+f"(d[1]), "+f"(d[2]), "+f"(d[3])          \
                 : "r"(a[0]), "r"(a[1]), "r"(a[2]), "r"(a[3]),             \
                   "r"(b0), "r"(b1))

#define LDSM_X4(r, a)                                                       \
    asm volatile("ldmatrix.sync.aligned.m8n8.x4.shared.b16 {%0,%1,%2,%3}, [%4];" \
                 : "=r"((r)[0]), "=r"((r)[1]), "=r"((r)[2]), "=r"((r)[3])   \
                 : "r"(a))

__device__ __forceinline__ void cpa16(uint32_t dst, const void* src) {
    asm volatile("cp.async.cg.shared.global [%0], [%1], 16;\n" :: "r"(dst), "l"(src));
}

#define GSTAGE_B 24576
#define GPLANE_B 6144

__device__ void gemm_tile(const GCfg& c, int tile, char* smemraw)
{
    bf16* smem = (bf16*)smemraw;
    const int tid  = threadIdx.x;
    const int lane = tid & 31, warp = tid >> 5;
    const int wm = warp >> 2, wn = warp & 3;
    const int g = lane >> 2, t = lane & 3;
    const int rowBase = (tile / c.nbx) * 128;
    const int colBase = (tile % c.nbx) * 128;

    if (c.inFlag) {
        const int rb = tile / c.nbx;
        if (c.rowWaitMul == 2) {
            spinwait(c.inFlag + 2 * rb, c.inNeed);
            spinwait(c.inFlag + 2 * rb + 1, c.inNeed);
        } else {
            spinwait(c.inFlag + rb, c.inNeed);
        }
        __threadfence();
    }

    const int lr = tid >> 1;
    const int lc = (tid & 1) * 8;
    const bf16* gAh = c.Ah + (size_t)(rowBase + lr) * c.lda + lc;
    const bf16* gAl = c.Al + (size_t)(rowBase + lr) * c.lda + lc;
    const bf16* gBh = c.Bh + (size_t)(colBase + lr) * c.K + lc;
    const bf16* gBl = c.Bl + (size_t)(colBase + lr) * c.K + lc;
    const uint32_t sbase = (uint32_t)__cvta_generic_to_shared(smem);
    const uint32_t sw = sbase + (lr * 24 + lc) * 2;

#define LOAD_STAGE(S, KT)                                       \
    do {                                                        \
        uint32_t b_ = sw + (S) * GSTAGE_B;                      \
        int ko_ = (KT) * 16;                                    \
        cpa16(b_,                gAh + ko_);                    \
        cpa16(b_ + GPLANE_B,     gAl + ko_);                    \
        cpa16(b_ + 2 * GPLANE_B, gBh + ko_);                    \
        cpa16(b_ + 3 * GPLANE_B, gBl + ko_);                    \
    } while (0)

    const int lq  = lane & 7;
    const int l8  = (lane >> 3) & 1;
    const int l16 = (lane >> 4) & 1;
    uint32_t offA[4], offB[2];
#pragma unroll
    for (int mi = 0; mi < 4; mi++)
        offA[mi] = ((wm * 64 + mi * 16 + lq + 8 * l8) * 24 + 8 * l16) * 2;
#pragma unroll
    for (int pi = 0; pi < 2; pi++)
        offB[pi] = ((wn * 32 + pi * 16 + lq + 8 * l16) * 24 + 8 * l8) * 2;

    float acc[4][4][4];
#pragma unroll
    for (int i = 0; i < 4; i++)
#pragma unroll
        for (int j = 0; j < 4; j++)
#pragma unroll
            for (int q = 0; q < 4; q++) acc[i][j][q] = 0.0f;

    const int KT = c.K >> 4;
    LOAD_STAGE(0, 0); asm volatile("cp.async.commit_group;");
    LOAD_STAGE(1, 1); asm volatile("cp.async.commit_group;");

    for (int kt = 0; kt < KT; ++kt) {
        asm volatile("cp.async.wait_group 1;" ::: "memory");
        __syncthreads();
        if (kt + 2 < KT) LOAD_STAGE((kt + 2) % 3, kt + 2);
        asm volatile("cp.async.commit_group;");

        const uint32_t st = sbase + (kt % 3) * GSTAGE_B;
        const uint32_t aH = st;
        const uint32_t aL = st + GPLANE_B;
        const uint32_t bH = st + 2 * GPLANE_B;
        const uint32_t bL = st + 3 * GPLANE_B;

        uint32_t a[4][4];
        uint32_t bh[4][2], bl[4][2];
#pragma unroll
        for (int mi = 0; mi < 4; mi++) LDSM_X4(a[mi], aH + offA[mi]);
        {
            uint32_t r4[4];
            LDSM_X4(r4, bH + offB[0]);
            bh[0][0] = r4[0]; bh[0][1] = r4[1];
            bh[1][0] = r4[2]; bh[1][1] = r4[3];
            LDSM_X4(r4, bH + offB[1]);
            bh[2][0] = r4[0]; bh[2][1] = r4[1];
            bh[3][0] = r4[2]; bh[3][1] = r4[3];
        }

#pragma unroll
        for (int mi = 0; mi < 4; mi++)
#pragma unroll
            for (int ni = 0; ni < 4; ni++)
                MMA_BF16(acc[mi][ni], a[mi], bh[ni][0], bh[ni][1]);

        {
            uint32_t r4[4];
            LDSM_X4(r4, bL + offB[0]);
            bl[0][0] = r4[0]; bl[0][1] = r4[1];
            bl[1][0] = r4[2]; bl[1][1] = r4[3];
            LDSM_X4(r4, bL + offB[1]);
            bl[2][0] = r4[0]; bl[2][1] = r4[1];
            bl[3][0] = r4[2]; bl[3][1] = r4[3];
        }

#pragma unroll
        for (int mi = 0; mi < 4; mi++)
#pragma unroll
            for (int ni = 0; ni < 4; ni++)
                MMA_BF16(acc[mi][ni], a[mi], bl[ni][0], bl[ni][1]);

#pragma unroll
        for (int mi = 0; mi < 4; mi++) LDSM_X4(a[mi], aL + offA[mi]);

#pragma unroll
        for (int mi = 0; mi < 4; mi++)
#pragma unroll
            for (int ni = 0; ni < 4; ni++)
                MMA_BF16(acc[mi][ni], a[mi], bh[ni][0], bh[ni][1]);
    }
#undef LOAD_STAGE

    const bool eBIAS = c.ebits & 1;
    const bool eRELU = c.ebits & 2;
    const bool eRES  = c.ebits & 4;
    const bool eWF   = c.ebits & 8;
    const bool eWB   = c.ebits & 16;

#pragma unroll
    for (int ni = 0; ni < 4; ni++) {
        const int cb = colBase + wn * 32 + ni * 8 + 2 * t;
        float b0 = 0.0f, b1 = 0.0f;
        if (eBIAS) { b0 = c.bias[cb]; b1 = c.bias[cb + 1]; }
#pragma unroll
        for (int mi = 0; mi < 4; mi++) {
#pragma unroll
            for (int hh = 0; hh < 2; hh++) {
                const int rr = rowBase + wm * 64 + mi * 16 + g + hh * 8;
                float v0 = acc[mi][ni][hh * 2 + 0];
                float v1 = acc[mi][ni][hh * 2 + 1];
                if (eBIAS) { v0 += b0; v1 += b1; }
                if (eRELU) { v0 = fmaxf(v0, 0.0f); v1 = fmaxf(v1, 0.0f); }
                if (eRES) {
                    const __nv_bfloat162 rh = *(const __nv_bfloat162*)&c.resh[(size_t)rr * c.N + cb];
                    const __nv_bfloat162 rl = *(const __nv_bfloat162*)&c.resl[(size_t)rr * c.N + cb];
                    v0 += __bfloat162float(rh.x) + __bfloat162float(rl.x);
                    v1 += __bfloat162float(rh.y) + __bfloat162float(rl.y);
                }
                if (eWF) {
                    float2 ov; ov.x = v0; ov.y = v1;
                    *(float2*)&c.Cf[(size_t)rr * c.N + cb] = ov;
                }
                if (eWB) {
                    bf16 h0, l0, h1, l1;
                    split2(v0, h0, l0); split2(v1, h1, l1);
                    __nv_bfloat162 ph; ph.x = h0; ph.y = h1;
                    __nv_bfloat162 pl; pl.x = l0; pl.y = l1;
                    *(__nv_bfloat162*)&c.Ch[(size_t)rr * c.N + cb] = ph;
                    *(__nv_bfloat162*)&c.Cl[(size_t)rr * c.N + cb] = pl;
                }
            }
        }
    }

    if (c.outFlag) {
        __threadfence();
        __syncthreads();
        if (tid == 0) atomicAdd(c.outFlag + tile / c.nbx, 1);
    }
}

// ---------------- attention block (8 bh per 256-thread block) ----------------
__device__ void attn_block(int aIdx, const float* __restrict__ QKV,
                           bf16* __restrict__ Oh, bf16* __restrict__ Ol,
                           const int* flagQ, int* flagO)
{
    const int w = aIdx * 8 + (threadIdx.x >> 5);
    const int lane = threadIdx.x & 31;
    const int b = w >> 4;
    const int h = w & 15;

    spinwait(flagQ + (b >> 6), 24);
    __threadfence();

    const size_t base = (size_t)(b * 2) * QKVN + h * HDIM + lane;
    float q0a = __ldcg(QKV + base),               q0b = __ldcg(QKV + base + 32);
    float q1a = __ldcg(QKV + base + QKVN),        q1b = __ldcg(QKV + base + QKVN + 32);
    float k0a = __ldcg(QKV + base + 1024),        k0b = __ldcg(QKV + base + 1056);
    float k1a = __ldcg(QKV + base + QKVN + 1024), k1b = __ldcg(QKV + base + QKVN + 1056);
    float v0a = __ldcg(QKV + base + 2048),        v0b = __ldcg(QKV + base + 2080);
    float v1a = __ldcg(QKV + base + QKVN + 2048), v1b = __ldcg(QKV + base + QKVN + 2080);

    float d00 = q0a * k0a + q0b * k0b;
    float d01 = q0a * k1a + q0b * k1b;
    float d10 = q1a * k0a + q1b * k0b;
    float d11 = q1a * k1a + q1b * k1b;
#pragma unroll
    for (int off = 16; off; off >>= 1) {
        d00 += __shfl_xor_sync(0xffffffffu, d00, off);
        d01 += __shfl_xor_sync(0xffffffffu, d01, off);
        d10 += __shfl_xor_sync(0xffffffffu, d10, off);
        d11 += __shfl_xor_sync(0xffffffffu, d11, off);
    }
    const float scale = 0.125f;
    float s00 = d00 * scale, s01 = d01 * scale;
    float s10 = d10 * scale, s11 = d11 * scale;
    float m0 = fmaxf(s00, s01), m1 = fmaxf(s10, s11);
    float e00 = expf(s00 - m0), e01 = expf(s01 - m0);
    float i0 = 1.0f / (e00 + e01);
    float e10 = expf(s10 - m1), e11 = expf(s11 - m1);
    float i1 = 1.0f / (e10 + e11);
    float p0 = e00 * i0, p1 = e01 * i0, p2 = e10 * i1, p3 = e11 * i1;

    const size_t o0 = (size_t)(b * 2) * EDIM + h * HDIM + lane;
    bf16 hh, ll;
    split2(p0 * v0a + p1 * v1a, hh, ll); Oh[o0] = hh;             Ol[o0] = ll;
    split2(p0 * v0b + p1 * v1b, hh, ll); Oh[o0 + 32] = hh;        Ol[o0 + 32] = ll;
    split2(p2 * v0a + p3 * v1a, hh, ll); Oh[o0 + EDIM] = hh;      Ol[o0 + EDIM] = ll;
    split2(p2 * v0b + p3 * v1b, hh, ll); Oh[o0 + EDIM + 32] = hh; Ol[o0 + EDIM + 32] = ll;

    __threadfence();
    __syncthreads();
    if (threadIdx.x == 0) atomicAdd(flagO + (aIdx >> 7), 1);
}

// ---------------- fused layer kernel ----------------
// queue: QKV(768) -> attn(4096) -> Wo(256) -> W1(1024) -> W2(256) -> [unembed]
__global__ void __launch_bounds__(256, 2)
layer_kernel(GCfg cQ, GCfg cWo, GCfg cW1, GCfg cW2, GCfg cUe,
             const float* QKV, bf16* Oh, bf16* Ol,
             int* flagQ, int* flagO, int nAttn)
{
    extern __shared__ char smem[];
    int bid = blockIdx.x;
    if (bid < cQ.nTiles)  { gemm_tile(cQ, bid, smem); return; }
    bid -= cQ.nTiles;
    if (bid < nAttn)      { attn_block(bid, QKV, Oh, Ol, flagQ, flagO); return; }
    bid -= nAttn;
    if (bid < cWo.nTiles) { gemm_tile(cWo, bid, smem); return; }
    bid -= cWo.nTiles;
    if (bid < cW1.nTiles) { gemm_tile(cW1, bid, smem); return; }
    bid -= cW1.nTiles;
    if (bid < cW2.nTiles) { gemm_tile(cW2, bid, smem); return; }
    bid -= cW2.nTiles;
    gemm_tile(cUe, bid, smem);
}

// ---------------- launcher ----------------
extern "C" void kernel_launch(void* const* d_in, const int* in_sizes, int n_in,
                              void* d_out, int out_size)
{
    (void)in_sizes; (void)n_in; (void)out_size;
    const int*   tokens  = (const int*)  d_in[0];
    const float* emb     = (const float*)d_in[1];
    const float* pos     = (const float*)d_in[2];
    const float* Wq      = (const float*)d_in[3];
    const float* Wk      = (const float*)d_in[4];
    const float* Wv      = (const float*)d_in[5];
    const float* Wo      = (const float*)d_in[6];
    const float* W1      = (const float*)d_in[7];
    const float* b1      = (const float*)d_in[8];
    const float* W2      = (const float*)d_in[9];
    const float* b2      = (const float*)d_in[10];
    const float* unembed = (const float*)d_in[11];
    float* out = (float*)d_out;

    bf16 *Wqkvh, *Wqkvl, *Woh, *Wol, *W1h, *W1l, *W2h, *W2l, *Ueh, *Uel;
    float *QKV;
    bf16 *Xh, *Xl, *X2h, *X2l, *Oh, *Ol, *H1h, *H1l;
    int* flags;
    cudaGetSymbolAddress((void**)&Wqkvh, g_Wqkv_h);
    cudaGetSymbolAddress((void**)&Wqkvl, g_Wqkv_l);
    cudaGetSymbolAddress((void**)&Woh,   g_Wo_h);
    cudaGetSymbolAddress((void**)&Wol,   g_Wo_l);
    cudaGetSymbolAddress((void**)&W1h,   g_W1_h);
    cudaGetSymbolAddress((void**)&W1l,   g_W1_l);
    cudaGetSymbolAddress((void**)&W2h,   g_W2_h);
    cudaGetSymbolAddress((void**)&W2l,   g_W2_l);
    cudaGetSymbolAddress((void**)&Ueh,   g_Ue_h);
    cudaGetSymbolAddress((void**)&Uel,   g_Ue_l);
    cudaGetSymbolAddress((void**)&QKV, g_QKV);
    cudaGetSymbolAddress((void**)&Xh,  g_Xh);
    cudaGetSymbolAddress((void**)&Xl,  g_Xl);
    cudaGetSymbolAddress((void**)&X2h, g_X2h);
    cudaGetSymbolAddress((void**)&X2l, g_X2l);
    cudaGetSymbolAddress((void**)&Oh,  g_Oh);
    cudaGetSymbolAddress((void**)&Ol,  g_Ol);
    cudaGetSymbolAddress((void**)&H1h, g_H1h);
    cudaGetSymbolAddress((void**)&H1l, g_H1l);
    cudaGetSymbolAddress((void**)&flags, g_flags);

    int* flagQ  = flags;
    int* flagO  = flags + 32;
    int* flagX2 = flags + 64;
    int* flagH1 = flags + 96;
    int* flagX  = flags + 128;

    const int SMEM = 3 * GSTAGE_B;
    cudaFuncSetAttribute(layer_kernel, cudaFuncAttributeMaxDynamicSharedMemorySize, SMEM);

    // ---- weight prep ----
    {
        dim3 b(32, 8);
        tconv_qkv_kernel<<<dim3(2, 16, NLAYER * 48), b>>>(Wq, Wk, Wv, Wqkvh, Wqkvl);
        tconv_kernel<<<dim3(32, 16, NLAYER), b>>>(Wo, Woh, Wol, EDIM, EDIM);
        tconv_kernel<<<dim3(128, 16, NLAYER), b>>>(W1, W1h, W1l, EDIM, HID);
        tconv_kernel<<<dim3(32, 64, NLAYER), b>>>(W2, W2h, W2l, HID, EDIM);
        tconv_kernel<<<dim3(1000, 16, 1), b>>>(unembed, Ueh, Uel, EDIM, VOC);
    }
    embed_kernel<<<(NTOK * EDIM / 4) / 256, 256>>>(tokens, emb, pos, Xh, Xl);

    GCfg z = {};   // zero template

    for (int l = 0; l < NLAYER; l++) {
        const bool last = (l == NLAYER - 1);

        GCfg cQ = z;
        cQ.Ah = Xh; cQ.Al = Xl; cQ.lda = EDIM;
        cQ.Bh = Wqkvh + (size_t)l * QKVN * EDIM;
        cQ.Bl = Wqkvl + (size_t)l * QKVN * EDIM;
        cQ.Cf = QKV;
        cQ.N = QKVN; cQ.K = EDIM; cQ.nbx = QKVN / 128; cQ.nTiles = (QKVN / 128) * (NTOK / 128);
        cQ.ebits = 8;                // WF32
        cQ.outFlag = flagQ;

        GCfg cWo = z;
        cWo.Ah = Oh; cWo.Al = Ol; cWo.lda = EDIM;
        cWo.Bh = Woh + (size_t)l * EDIM * EDIM;
        cWo.Bl = Wol + (size_t)l * EDIM * EDIM;
        cWo.resh = Xh; cWo.resl = Xl;
        cWo.Ch = X2h; cWo.Cl = X2l;
        cWo.N = EDIM; cWo.K = EDIM; cWo.nbx = EDIM / 128; cWo.nTiles = (EDIM / 128) * (NTOK / 128);
        cWo.ebits = 4 | 16;          // RES | WBF
        cWo.outFlag = flagX2;
        cWo.inFlag = flagO; cWo.inNeed = 128; cWo.rowWaitMul = 1;

        GCfg cW1 = z;
        cW1.Ah = X2h; cW1.Al = X2l; cW1.lda = EDIM;
        cW1.Bh = W1h + (size_t)l * HID * EDIM;
        cW1.Bl = W1l + (size_t)l * HID * EDIM;
        cW1.bias = b1 + (size_t)l * HID;
        cW1.Ch = H1h; cW1.Cl = H1l;
        cW1.N = HID; cW1.K = EDIM; cW1.nbx = HID / 128; cW1.nTiles = (HID / 128) * (NTOK / 128);
        cW1.ebits = 1 | 2 | 16;      // BIAS | RELU | WBF
        cW1.outFlag = flagH1;
        cW1.inFlag = flagX2; cW1.inNeed = 8; cW1.rowWaitMul = 1;

        GCfg cW2 = z;
        cW2.Ah = H1h; cW2.Al = H1l; cW2.lda = HID;
        cW2.Bh = W2h + (size_t)l * EDIM * HID;
        cW2.Bl = W2l + (size_t)l * EDIM * HID;
        cW2.bias = b2 + (size_t)l * EDIM;
        cW2.resh = X2h; cW2.resl = X2l;
        cW2.Ch = Xh; cW2.Cl = Xl;
        cW2.N = EDIM; cW2.K = HID; cW2.nbx = EDIM / 128; cW2.nTiles = (EDIM / 128) * (NTOK / 128);
        cW2.ebits = 1 | 2 | 4 | 16;  // BIAS | RELU | RES | WBF
        cW2.inFlag = flagH1; cW2.inNeed = 32; cW2.rowWaitMul = 1;
        if (last) cW2.outFlag = flagX;

        GCfg cUe = z;
        int nUe = 0;
        if (last) {
            cUe.Ah = Xh + EDIM; cUe.Al = Xl + EDIM; cUe.lda = 2 * EDIM;
            cUe.Bh = Ueh; cUe.Bl = Uel;
            cUe.Cf = out;
            cUe.N = VOC; cUe.K = EDIM; cUe.nbx = VOC / 128; cUe.nTiles = (VOC / 128) * (BATCH / 128);
            cUe.ebits = 8;           // WF32
            cUe.inFlag = flagX; cUe.inNeed = 8; cUe.rowWaitMul = 2;
            nUe = cUe.nTiles;
        }

        const int nAttn = BATCH * NHEAD / 8;   // 4096
        const int grid = cQ.nTiles + nAttn + cWo.nTiles + cW1.nTiles + cW2.nTiles + nUe;

        cudaMemsetAsync(flags, 0, 160 * sizeof(int), 0);
        layer_kernel<<<grid, 256, SMEM>>>(cQ, cWo, cW1, cW2, cUe,
                                          QKV, Oh, Ol, flagQ, flagO, nAttn);
    }
}

// round 15
// speedup vs baseline: 1.0134x; 1.0134x over previous
#include <cuda_runtime.h>
#include <cuda_bf16.h>
#include <cstdint>
#include <math.h>

#define NTOK 4096
#define EDIM 1024
#define HID  4096
#define NLAYER 12
#define NHEAD 16
#define HDIM 64
#define BATCH 2048
#define VOC  32000
#define QKVN 3072

typedef __nv_bfloat16 bf16;

struct alignas(8) bf4 { __nv_bfloat162 a, b; };

// ---------------- scratch (device globals) ----------------
__device__ bf16 g_Wqkv_h[NLAYER * QKVN * EDIM];
__device__ bf16 g_Wqkv_l[NLAYER * QKVN * EDIM];
__device__ bf16 g_Wo_h [NLAYER * EDIM * EDIM];
__device__ bf16 g_Wo_l [NLAYER * EDIM * EDIM];
__device__ bf16 g_W1_h [NLAYER * HID * EDIM];
__device__ bf16 g_W1_l [NLAYER * HID * EDIM];
__device__ bf16 g_W2_h [NLAYER * EDIM * HID];
__device__ bf16 g_W2_l [NLAYER * EDIM * HID];
__device__ bf16 g_Ue_h [VOC * EDIM];
__device__ bf16 g_Ue_l [VOC * EDIM];
__device__ float g_QKV[NTOK * QKVN];     // also reused as split-K partials (2 x NTOK*EDIM)
__device__ bf16  g_Xh [NTOK * EDIM];
__device__ bf16  g_Xl [NTOK * EDIM];
__device__ bf16  g_X2h[NTOK * EDIM];
__device__ bf16  g_X2l[NTOK * EDIM];
__device__ bf16  g_Oh [NTOK * EDIM];
__device__ bf16  g_Ol [NTOK * EDIM];
__device__ bf16  g_H1h[NTOK * HID];
__device__ bf16  g_H1l[NTOK * HID];

__device__ __forceinline__ void split2(float v, bf16& h, bf16& l) {
    h = __float2bfloat16(v);
    l = __float2bfloat16(v - __bfloat162float(h));
}

// ---------------- weight transpose + split ----------------
__global__ void tconv_kernel(const float* __restrict__ src,
                             bf16* __restrict__ dhi, bf16* __restrict__ dlo,
                             int K, int N)
{
    __shared__ float t[64][33];
    const int z = blockIdx.z;
    src += (size_t)z * K * N;
    dhi += (size_t)z * K * N;
    dlo += (size_t)z * K * N;
    const int k0 = blockIdx.y * 64, n0 = blockIdx.x * 32;
    const int tx = threadIdx.x, ty = threadIdx.y;
#pragma unroll
    for (int j = 0; j < 8; j++)
        t[ty + 8 * j][tx] = src[(size_t)(k0 + ty + 8 * j) * N + n0 + tx];
    __syncthreads();
    const int s  = ty * 32 + tx;
    const int kq = s & 15;
    const int nb = s >> 4;
#pragma unroll
    for (int j = 0; j < 2; j++) {
        const int n = nb + 16 * j;
        float v0 = t[4 * kq + 0][n];
        float v1 = t[4 * kq + 1][n];
        float v2 = t[4 * kq + 2][n];
        float v3 = t[4 * kq + 3][n];
        bf16 h0, l0, h1, l1, h2, l2, h3, l3;
        split2(v0, h0, l0); split2(v1, h1, l1);
        split2(v2, h2, l2); split2(v3, h3, l3);
        bf4 ph, pl;
        ph.a.x = h0; ph.a.y = h1; ph.b.x = h2; ph.b.y = h3;
        pl.a.x = l0; pl.a.y = l1; pl.b.x = l2; pl.b.y = l3;
        size_t o = (size_t)(n0 + n) * K + k0 + 4 * kq;
        *(bf4*)&dhi[o] = ph;
        *(bf4*)&dlo[o] = pl;
    }
}

__global__ void tconv_qkv_kernel(const float* __restrict__ Wq,
                                 const float* __restrict__ Wk,
                                 const float* __restrict__ Wv,
                                 bf16* __restrict__ dhi, bf16* __restrict__ dlo)
{
    __shared__ float t[64][33];
    const int z = blockIdx.z;
    const int l = z / 48;
    const int rr = z % 48;
    const int which = rr / 16;
    const int h = rr % 16;
    const float* src = (which == 0 ? Wq : which == 1 ? Wk : Wv)
                       + ((size_t)(l * NHEAD + h) * EDIM) * HDIM;
    const int i0 = blockIdx.x * 32;
    const int k0 = blockIdx.y * 64;
    const int tx = threadIdx.x, ty = threadIdx.y;
#pragma unroll
    for (int j = 0; j < 8; j++)
        t[ty + 8 * j][tx] = src[(size_t)(k0 + ty + 8 * j) * HDIM + i0 + tx];
    __syncthreads();
    bf16* bh = dhi + (size_t)l * QKVN * EDIM;
    bf16* bl = dlo + (size_t)l * QKVN * EDIM;
    const int s  = ty * 32 + tx;
    const int kq = s & 15;
    const int nb = s >> 4;
#pragma unroll
    for (int j = 0; j < 2; j++) {
        const int ni = nb + 16 * j;
        float v0 = t[4 * kq + 0][ni];
        float v1 = t[4 * kq + 1][ni];
        float v2 = t[4 * kq + 2][ni];
        float v3 = t[4 * kq + 3][ni];
        bf16 h0, l0, h1, l1, h2, l2, h3, l3;
        split2(v0, h0, l0); split2(v1, h1, l1);
        split2(v2, h2, l2); split2(v3, h3, l3);
        bf4 ph, pl;
        ph.a.x = h0; ph.a.y = h1; ph.b.x = h2; ph.b.y = h3;
        pl.a.x = l0; pl.a.y = l1; pl.b.x = l2; pl.b.y = l3;
        int n = which * 1024 + h * 64 + i0 + ni;
        size_t o = (size_t)n * EDIM + k0 + 4 * kq;
        *(bf4*)&bh[o] = ph;
        *(bf4*)&bl[o] = pl;
    }
}

// ---------------- embedding (planes only) ----------------
__global__ void embed_kernel(const int* __restrict__ tokens,
                             const float* __restrict__ emb,
                             const float* __restrict__ pos,
                             bf16* __restrict__ Xh, bf16* __restrict__ Xl)
{
    int idx = blockIdx.x * blockDim.x + threadIdx.x;
    int i  = idx / (EDIM / 4);
    int e4 = idx % (EDIM / 4);
    int tok = tokens[i];
    float4 a = ((const float4*)(emb + (size_t)tok * EDIM))[e4];
    float4 p = ((const float4*)(pos + (size_t)(i & 1) * EDIM))[e4];
    float r[4] = { a.x + p.x, a.y + p.y, a.z + p.z, a.w + p.w };
    bf16 hh[4], ll[4];
#pragma unroll
    for (int j = 0; j < 4; j++) split2(r[j], hh[j], ll[j]);
    bf4 ph, pl;
    ph.a.x = hh[0]; ph.a.y = hh[1]; ph.b.x = hh[2]; ph.b.y = hh[3];
    pl.a.x = ll[0]; pl.a.y = ll[1]; pl.b.x = ll[2]; pl.b.y = ll[3];
    size_t o = (size_t)i * EDIM + e4 * 4;
    *(bf4*)&Xh[o] = ph;
    *(bf4*)&Xl[o] = pl;
}

// ---------------- attention (T=2): one warp per (b,h), no smem ----------------
__global__ void attn_kernel(const float* __restrict__ QKV,
                            bf16* __restrict__ Oh, bf16* __restrict__ Ol)
{
    const int w = blockIdx.x * 8 + (threadIdx.x >> 5);
    const int lane = threadIdx.x & 31;
    const int b = w >> 4;
    const int h = w & 15;
    const size_t base = (size_t)(b * 2) * QKVN + h * HDIM + lane;

    float q0a = QKV[base],               q0b = QKV[base + 32];
    float q1a = QKV[base + QKVN],        q1b = QKV[base + QKVN + 32];
    float k0a = QKV[base + 1024],        k0b = QKV[base + 1056];
    float k1a = QKV[base + QKVN + 1024], k1b = QKV[base + QKVN + 1056];
    float v0a = QKV[base + 2048],        v0b = QKV[base + 2080];
    float v1a = QKV[base + QKVN + 2048], v1b = QKV[base + QKVN + 2080];

    float d00 = q0a * k0a + q0b * k0b;
    float d01 = q0a * k1a + q0b * k1b;
    float d10 = q1a * k0a + q1b * k0b;
    float d11 = q1a * k1a + q1b * k1b;
#pragma unroll
    for (int off = 16; off; off >>= 1) {
        d00 += __shfl_xor_sync(0xffffffffu, d00, off);
        d01 += __shfl_xor_sync(0xffffffffu, d01, off);
        d10 += __shfl_xor_sync(0xffffffffu, d10, off);
        d11 += __shfl_xor_sync(0xffffffffu, d11, off);
    }
    const float scale = 0.125f;
    float s00 = d00 * scale, s01 = d01 * scale;
    float s10 = d10 * scale, s11 = d11 * scale;
    float m0 = fmaxf(s00, s01), m1 = fmaxf(s10, s11);
    float e00 = expf(s00 - m0), e01 = expf(s01 - m0);
    float i0 = 1.0f / (e00 + e01);
    float e10 = expf(s10 - m1), e11 = expf(s11 - m1);
    float i1 = 1.0f / (e10 + e11);
    float p0 = e00 * i0, p1 = e01 * i0, p2 = e10 * i1, p3 = e11 * i1;

    const size_t o0 = (size_t)(b * 2) * EDIM + h * HDIM + lane;
    bf16 hh, ll;
    split2(p0 * v0a + p1 * v1a, hh, ll); Oh[o0] = hh;             Ol[o0] = ll;
    split2(p0 * v0b + p1 * v1b, hh, ll); Oh[o0 + 32] = hh;        Ol[o0 + 32] = ll;
    split2(p2 * v0a + p3 * v1a, hh, ll); Oh[o0 + EDIM] = hh;      Ol[o0 + EDIM] = ll;
    split2(p2 * v0b + p3 * v1b, hh, ll); Oh[o0 + EDIM + 32] = hh; Ol[o0 + EDIM + 32] = ll;
}

// ---------------- split-K combine: X = relu(p0+p1+bias) + X2, emit planes ----------------
__global__ void combine_kernel(const float* __restrict__ part,
                               const float* __restrict__ bias,
                               const bf16* __restrict__ resh,
                               const bf16* __restrict__ resl,
                               bf16* __restrict__ Xh, bf16* __restrict__ Xl)
{
    const int idx = blockIdx.x * blockDim.x + threadIdx.x;   // over NTOK*EDIM/4
    const size_t o = (size_t)idx * 4;
    const int col = (o & (EDIM - 1));
    float4 p0 = *(const float4*)&part[o];
    float4 p1 = *(const float4*)&part[o + (size_t)NTOK * EDIM];
    float4 bb = *(const float4*)&bias[col];
    bf4 rh = *(const bf4*)&resh[o];
    bf4 rl = *(const bf4*)&resl[o];
    float v[4];
    v[0] = fmaxf(p0.x + p1.x + bb.x, 0.0f) + __bfloat162float(rh.a.x) + __bfloat162float(rl.a.x);
    v[1] = fmaxf(p0.y + p1.y + bb.y, 0.0f) + __bfloat162float(rh.a.y) + __bfloat162float(rl.a.y);
    v[2] = fmaxf(p0.z + p1.z + bb.z, 0.0f) + __bfloat162float(rh.b.x) + __bfloat162float(rl.b.x);
    v[3] = fmaxf(p0.w + p1.w + bb.w, 0.0f) + __bfloat162float(rh.b.y) + __bfloat162float(rl.b.y);
    bf16 hh[4], ll[4];
#pragma unroll
    for (int j = 0; j < 4; j++) split2(v[j], hh[j], ll[j]);
    bf4 ph, pl;
    ph.a.x = hh[0]; ph.a.y = hh[1]; ph.b.x = hh[2]; ph.b.y = hh[3];
    pl.a.x = ll[0]; pl.a.y = ll[1]; pl.b.x = ll[2]; pl.b.y = ll[3];
    *(bf4*)&Xh[o] = ph;
    *(bf4*)&Xl[o] = pl;
}

// ---------------- 3xBF16 tensor-core GEMM (champion mainloop) ----------------
#define MMA_BF16(d, a, b0, b1)                                             \
    asm volatile("mma.sync.aligned.m16n8k16.row.col.f32.bf16.bf16.f32 "    \
                 "{%0,%1,%2,%3},{%4,%5,%6,%7},{%8,%9},{%0,%1,%2,%3};"      \
                 : "+f"(d[0]), "+f"(d[1]), "+f"(d[2]), "+f"(d[3])          \
                 : "r"(a[0]), "r"(a[1]), "r"(a[2]), "r"(a[3]),             \
                   "r"(b0), "r"(b1))

#define LDSM_X4(r, a)                                                       \
    asm volatile("ldmatrix.sync.aligned.m8n8.x4.shared.b16 {%0,%1,%2,%3}, [%4];" \
                 : "=r"((r)[0]), "=r"((r)[1]), "=r"((r)[2]), "=r"((r)[3])   \
                 : "r"(a))

__device__ __forceinline__ void cpa16(uint32_t dst, const void* src) {
    asm volatile("cp.async.cg.shared.global [%0], [%1], 16;\n" :: "r"(dst), "l"(src));
}

#define GSTAGE_B 24576
#define GPLANE_B 6144

// K = k-extent THIS block accumulates; ldb = B row stride (full K of the matrix).
// blockIdx.z selects the K-half: offsets A,B by z*K and Cf by z*partStride.
template<bool BIAS, bool RELU, bool RES, bool WF32, bool WBF>
__global__ void __launch_bounds__(256, 2)
gemm3_kernel(const bf16* __restrict__ Ah_, const bf16* __restrict__ Al_, int lda,
             const bf16* __restrict__ Bh_, const bf16* __restrict__ Bl_, int ldb,
             const float* __restrict__ bias,
             const bf16* __restrict__ resh, const bf16* __restrict__ resl,
             float* __restrict__ Cf, bf16* __restrict__ Ch, bf16* __restrict__ Cl,
             int N, int K, size_t partStride)
{
    extern __shared__ bf16 smem[];
    const int tid  = threadIdx.x;
    const int lane = tid & 31, warp = tid >> 5;
    const int wm = warp >> 2, wn = warp & 3;
    const int g = lane >> 2, t = lane & 3;
    const int rowBase = blockIdx.y * 128;
    const int colBase = blockIdx.x * 128;
    const int kh = blockIdx.z;
    Ah_ += (size_t)kh * K;
    Al_ += (size_t)kh * K;
    Bh_ += (size_t)kh * K;
    Bl_ += (size_t)kh * K;
    Cf  += (size_t)kh * partStride;

    const int lr = tid >> 1;
    const int lc = (tid & 1) * 8;
    const bf16* gAh = Ah_ + (size_t)(rowBase + lr) * lda + lc;
    const bf16* gAl = Al_ + (size_t)(rowBase + lr) * lda + lc;
    const bf16* gBh = Bh_ + (size_t)(colBase + lr) * ldb + lc;
    const bf16* gBl = Bl_ + (size_t)(colBase + lr) * ldb + lc;
    const uint32_t sbase = (uint32_t)__cvta_generic_to_shared(smem);
    const uint32_t sw = sbase + (lr * 24 + lc) * 2;

#define LOAD_STAGE(S, KT)                                       \
    do {                                                        \
        uint32_t b_ = sw + (S) * GSTAGE_B;                      \
        int ko_ = (KT) * 16;                                    \
        cpa16(b_,                gAh + ko_);                    \
        cpa16(b_ + GPLANE_B,     gAl + ko_);                    \
        cpa16(b_ + 2 * GPLANE_B, gBh + ko_);                    \
        cpa16(b_ + 3 * GPLANE_B, gBl + ko_);                    \
    } while (0)

    const int lq  = lane & 7;
    const int l8  = (lane >> 3) & 1;
    const int l16 = (lane >> 4) & 1;
    uint32_t offA[4], offB[2];
#pragma unroll
    for (int mi = 0; mi < 4; mi++)
        offA[mi] = ((wm * 64 + mi * 16 + lq + 8 * l8) * 24 + 8 * l16) * 2;
#pragma unroll
    for (int pi = 0; pi < 2; pi++)
        offB[pi] = ((wn * 32 + pi * 16 + lq + 8 * l16) * 24 + 8 * l8) * 2;

    float acc[4][4][4];
#pragma unroll
    for (int i = 0; i < 4; i++)
#pragma unroll
        for (int j = 0; j < 4; j++)
#pragma unroll
            for (int q = 0; q < 4; q++) acc[i][j][q] = 0.0f;

    const int KT = K >> 4;
    LOAD_STAGE(0, 0); asm volatile("cp.async.commit_group;");
    LOAD_STAGE(1, 1); asm volatile("cp.async.commit_group;");

    for (int kt = 0; kt < KT; ++kt) {
        asm volatile("cp.async.wait_group 1;" ::: "memory");
        __syncthreads();
        if (kt + 2 < KT) LOAD_STAGE((kt + 2) % 3, kt + 2);
        asm volatile("cp.async.commit_group;");

        const uint32_t st = sbase + (kt % 3) * GSTAGE_B;
        const uint32_t aH = st;
        const uint32_t aL = st + GPLANE_B;
        const uint32_t bH = st + 2 * GPLANE_B;
        const uint32_t bL = st + 3 * GPLANE_B;

        uint32_t a[4][4];
        uint32_t bh[4][2], bl[4][2];
#pragma unroll
        for (int mi = 0; mi < 4; mi++) LDSM_X4(a[mi], aH + offA[mi]);
        {
            uint32_t r4[4];
            LDSM_X4(r4, bH + offB[0]);
            bh[0][0] = r4[0]; bh[0][1] = r4[1];
            bh[1][0] = r4[2]; bh[1][1] = r4[3];
            LDSM_X4(r4, bH + offB[1]);
            bh[2][0] = r4[0]; bh[2][1] = r4[1];
            bh[3][0] = r4[2]; bh[3][1] = r4[3];
        }

#pragma unroll
        for (int mi = 0; mi < 4; mi++)
#pragma unroll
            for (int ni = 0; ni < 4; ni++)
                MMA_BF16(acc[mi][ni], a[mi], bh[ni][0], bh[ni][1]);

        {
            uint32_t r4[4];
            LDSM_X4(r4, bL + offB[0]);
            bl[0][0] = r4[0]; bl[0][1] = r4[1];
            bl[1][0] = r4[2]; bl[1][1] = r4[3];
            LDSM_X4(r4, bL + offB[1]);
            bl[2][0] = r4[0]; bl[2][1] = r4[1];
            bl[3][0] = r4[2]; bl[3][1] = r4[3];
        }

#pragma unroll
        for (int mi = 0; mi < 4; mi++)
#pragma unroll
            for (int ni = 0; ni < 4; ni++)
                MMA_BF16(acc[mi][ni], a[mi], bl[ni][0], bl[ni][1]);

#pragma unroll
        for (int mi = 0; mi < 4; mi++) LDSM_X4(a[mi], aL + offA[mi]);

#pragma unroll
        for (int mi = 0; mi < 4; mi++)
#pragma unroll
            for (int ni = 0; ni < 4; ni++)
                MMA_BF16(acc[mi][ni], a[mi], bh[ni][0], bh[ni][1]);
    }
#undef LOAD_STAGE

    // epilogue
#pragma unroll
    for (int ni = 0; ni < 4; ni++) {
        const int cb = colBase + wn * 32 + ni * 8 + 2 * t;
        float b0 = 0.0f, b1 = 0.0f;
        if (BIAS) { b0 = bias[cb]; b1 = bias[cb + 1]; }
#pragma unroll
        for (int mi = 0; mi < 4; mi++) {
#pragma unroll
            for (int hh = 0; hh < 2; hh++) {
                const int rr = rowBase + wm * 64 + mi * 16 + g + hh * 8;
                float v0 = acc[mi][ni][hh * 2 + 0];
                float v1 = acc[mi][ni][hh * 2 + 1];
                if (BIAS) { v0 += b0; v1 += b1; }
                if (RELU) { v0 = fmaxf(v0, 0.0f); v1 = fmaxf(v1, 0.0f); }
                if (RES) {
                    const __nv_bfloat162 rh = *(const __nv_bfloat162*)&resh[(size_t)rr * N + cb];
                    const __nv_bfloat162 rl = *(const __nv_bfloat162*)&resl[(size_t)rr * N + cb];
                    v0 += __bfloat162float(rh.x) + __bfloat162float(rl.x);
                    v1 += __bfloat162float(rh.y) + __bfloat162float(rl.y);
                }
                if (WF32) {
                    float2 ov; ov.x = v0; ov.y = v1;
                    *(float2*)&Cf[(size_t)rr * N + cb] = ov;
                }
                if (WBF) {
                    bf16 h0, l0, h1, l1;
                    split2(v0, h0, l0); split2(v1, h1, l1);
                    __nv_bfloat162 ph; ph.x = h0; ph.y = h1;
                    __nv_bfloat162 pl; pl.x = l0; pl.y = l1;
                    *(__nv_bfloat162*)&Ch[(size_t)rr * N + cb] = ph;
                    *(__nv_bfloat162*)&Cl[(size_t)rr * N + cb] = pl;
                }
            }
        }
    }
}

// ---------------- launcher ----------------
extern "C" void kernel_launch(void* const* d_in, const int* in_sizes, int n_in,
                              void* d_out, int out_size)
{
    (void)in_sizes; (void)n_in; (void)out_size;
    const int*   tokens  = (const int*)  d_in[0];
    const float* emb     = (const float*)d_in[1];
    const float* pos     = (const float*)d_in[2];
    const float* Wq      = (const float*)d_in[3];
    const float* Wk      = (const float*)d_in[4];
    const float* Wv      = (const float*)d_in[5];
    const float* Wo      = (const float*)d_in[6];
    const float* W1      = (const float*)d_in[7];
    const float* b1      = (const float*)d_in[8];
    const float* W2      = (const float*)d_in[9];
    const float* b2      = (const float*)d_in[10];
    const float* unembed = (const float*)d_in[11];
    float* out = (float*)d_out;

    bf16 *Wqkvh, *Wqkvl, *Woh, *Wol, *W1h, *W1l, *W2h, *W2l, *Ueh, *Uel;
    float *QKV;
    bf16 *Xh, *Xl, *X2h, *X2l, *Oh, *Ol, *H1h, *H1l;
    cudaGetSymbolAddress((void**)&Wqkvh, g_Wqkv_h);
    cudaGetSymbolAddress((void**)&Wqkvl, g_Wqkv_l);
    cudaGetSymbolAddress((void**)&Woh,   g_Wo_h);
    cudaGetSymbolAddress((void**)&Wol,   g_Wo_l);
    cudaGetSymbolAddress((void**)&W1h,   g_W1_h);
    cudaGetSymbolAddress((void**)&W1l,   g_W1_l);
    cudaGetSymbolAddress((void**)&W2h,   g_W2_h);
    cudaGetSymbolAddress((void**)&W2l,   g_W2_l);
    cudaGetSymbolAddress((void**)&Ueh,   g_Ue_h);
    cudaGetSymbolAddress((void**)&Uel,   g_Ue_l);
    cudaGetSymbolAddress((void**)&QKV, g_QKV);
    cudaGetSymbolAddress((void**)&Xh,  g_Xh);
    cudaGetSymbolAddress((void**)&Xl,  g_Xl);
    cudaGetSymbolAddress((void**)&X2h, g_X2h);
    cudaGetSymbolAddress((void**)&X2l, g_X2l);
    cudaGetSymbolAddress((void**)&Oh,  g_Oh);
    cudaGetSymbolAddress((void**)&Ol,  g_Ol);
    cudaGetSymbolAddress((void**)&H1h, g_H1h);
    cudaGetSymbolAddress((void**)&H1l, g_H1l);

    const int SMEM = 3 * GSTAGE_B;
    cudaFuncSetAttribute(gemm3_kernel<false, false, false, true,  false>,
                         cudaFuncAttributeMaxDynamicSharedMemorySize, SMEM);
    cudaFuncSetAttribute(gemm3_kernel<false, false, true,  false, true >,
                         cudaFuncAttributeMaxDynamicSharedMemorySize, SMEM);
    cudaFuncSetAttribute(gemm3_kernel<true,  true,  false, false, true >,
                         cudaFuncAttributeMaxDynamicSharedMemorySize, SMEM);

    // ---- weight prep (transpose + bf16 split) ----
    {
        dim3 b(32, 8);
        tconv_qkv_kernel<<<dim3(2, 16, NLAYER * 48), b>>>(Wq, Wk, Wv, Wqkvh, Wqkvl);
        tconv_kernel<<<dim3(32, 16, NLAYER), b>>>(Wo, Woh, Wol, EDIM, EDIM);
        tconv_kernel<<<dim3(128, 16, NLAYER), b>>>(W1, W1h, W1l, EDIM, HID);
        tconv_kernel<<<dim3(32, 64, NLAYER), b>>>(W2, W2h, W2l, HID, EDIM);
        tconv_kernel<<<dim3(1000, 16, 1), b>>>(unembed, Ueh, Uel, EDIM, VOC);
    }

    embed_kernel<<<(NTOK * EDIM / 4) / 256, 256>>>(tokens, emb, pos, Xh, Xl);

    const dim3 blk(256);
    const size_t PART = (size_t)NTOK * EDIM;
    for (int l = 0; l < NLAYER; l++) {
        const bf16* wqh = Wqkvh + (size_t)l * QKVN * EDIM;
        const bf16* wql = Wqkvl + (size_t)l * QKVN * EDIM;
        const bf16* woh = Woh + (size_t)l * EDIM * EDIM;
        const bf16* wol = Wol + (size_t)l * EDIM * EDIM;
        const bf16* w1h = W1h + (size_t)l * HID * EDIM;
        const bf16* w1l = W1l + (size_t)l * HID * EDIM;
        const bf16* w2h = W2h + (size_t)l * EDIM * HID;
        const bf16* w2l = W2l + (size_t)l * EDIM * HID;
        const float* b1l = b1 + (size_t)l * HID;
        const float* b2l = b2 + (size_t)l * EDIM;

        // QKV = X @ Wqkv  [4096, 3072] -> f32
        gemm3_kernel<false, false, false, true, false>
            <<<dim3(QKVN / 128, NTOK / 128), blk, SMEM>>>(
            Xh, Xl, EDIM, wqh, wql, EDIM, nullptr, nullptr, nullptr,
            QKV, nullptr, nullptr, QKVN, EDIM, 0);

        attn_kernel<<<BATCH * NHEAD / 8, 256>>>(QKV, Oh, Ol);

        // X2 = O @ Wo + X  [4096, 1024]  (planes; residual from X planes)
        gemm3_kernel<false, false, true, false, true>
            <<<dim3(EDIM / 128, NTOK / 128), blk, SMEM>>>(
            Oh, Ol, EDIM, woh, wol, EDIM, nullptr, Xh, Xl,
            nullptr, X2h, X2l, EDIM, EDIM, 0);

        // H1 = relu(X2 @ W1 + b1)  [4096, 4096]  (planes)
        gemm3_kernel<true, true, false, false, true>
            <<<dim3(HID / 128, NTOK / 128), blk, SMEM>>>(
            X2h, X2l, EDIM, w1h, w1l, EDIM, b1l, nullptr, nullptr,
            nullptr, H1h, H1l, HID, EDIM, 0);

        // W2 split-K: partials p_z = H1[:, z*2048:(z+1)*2048] @ W2[z half]  (f32, into QKV buffer)
        gemm3_kernel<false, false, false, true, false>
            <<<dim3(EDIM / 128, NTOK / 128, 2), blk, SMEM>>>(
            H1h, H1l, HID, w2h, w2l, HID, nullptr, nullptr, nullptr,
            QKV, nullptr, nullptr, EDIM, HID / 2, PART);

        // X = relu(p0+p1+b2) + X2  (planes)
        combine_kernel<<<(NTOK * EDIM / 4) / 256, 256>>>(QKV, b2l, X2h, X2l, Xh, Xl);
    }

    // logits = X[:, odd rows, :] @ unembed  [2048, 32000] -> f32 out
    gemm3_kernel<false, false, false, true, false>
        <<<dim3(VOC / 128, BATCH / 128), blk, SMEM>>>(
        Xh + EDIM, Xl + EDIM, 2 * EDIM, Ueh, Uel, EDIM, nullptr, nullptr, nullptr,
        out, nullptr, nullptr, VOC, EDIM, 0);
}